// round 7
// baseline (speedup 1.0000x reference)
#include <cuda_runtime.h>
#include <cuda_bf16.h>

// PartialMatchingLoss: mean over partial points of min Euclidean distance to
// completed points (per batch). B=8, M=4096, N=8192, D=3.
//
// min_n d^2 = ||p||^2 + min_n (||c||^2 - 2 p.c).
// Packed axis = completed points: smem holds {x_2j,x_2j+1},{y,y'},{z,z'},{w,w'}
// (16 B/point). Queries duplicated into packed registers once (free).
// Per 2 completed points per query: 3 fma.rn.f32x2 (fma pipe) + 2 FMNMX (alu).

#define B_ 8
#define M_ 4096
#define N_ 8192

#define THREADS 128
#define Q 4                          // queries per thread (occupancy-tuned)
#define MCHUNK (THREADS * Q)         // 512 queries per CTA
#define NMCHUNK (M_ / MCHUNK)        // 8
#define NSPLIT 32
#define NTILE (N_ / NSPLIT)          // 256 completed points per tile
#define NGROUP (NTILE / 2)           // 128 packed point-pairs
#define K1_GRID (B_ * NMCHUNK * NSPLIT) // 2048 CTAs

#define TOTAL_P (B_ * M_)            // 32768
#define K2_THREADS 256
#define K2_GRID (TOTAL_P / K2_THREADS) // 128

// Scratch (no allocation allowed): every slot written unconditionally each
// launch; counter returns to 0 at end of each launch -> deterministic replays.
__device__ float g_minbuf[NSPLIT][TOTAL_P];   // 4 MB
__device__ float g_blocksum[K2_GRID];
__device__ unsigned int g_cnt;                 // zero-init at module load

#define FMA_F32X2(d, a, b, c) \
    asm("fma.rn.f32x2 %0, %1, %2, %3;" : "=l"(d) : "l"(a), "l"(b), "l"(c))

__device__ __forceinline__ unsigned long long pk2(float a, float b) {
    unsigned long long r;
    asm("mov.b64 %0, {%1, %2};" : "=l"(r) : "f"(a), "f"(b));
    return r;
}
__device__ __forceinline__ void unpk2(float& lo, float& hi, unsigned long long v) {
    asm("mov.b64 {%0, %1}, %2;" : "=f"(lo), "=f"(hi) : "l"(v));
}

__global__ void __launch_bounds__(THREADS, 9)
k1_min_tile(const float* __restrict__ completed, const float* __restrict__ partial) {
    // Group g (points 2g, 2g+1):
    //   sxy[g] = { {x,x'}, {y,y'} },  szw[g] = { {z,z'}, {w,w'} }   (w = ||c||^2)
    __shared__ ulonglong2 sxy[NGROUP];   // 2 KB
    __shared__ ulonglong2 szw[NGROUP];   // 2 KB

    const int bid = blockIdx.x;
    const int ns  = bid & (NSPLIT - 1);
    const int r   = bid >> 5;
    const int mc  = r & (NMCHUNK - 1);
    const int b   = r >> 3;
    const int tid = threadIdx.x;

    // Stage tile: thread g packs point-pair g (NGROUP == THREADS -> 1 pass).
    {
        const float* cg = completed + ((size_t)b * N_ + (size_t)ns * NTILE + 2 * tid) * 3;
        float x0 = cg[0], y0 = cg[1], z0 = cg[2];
        float x1 = cg[3], y1 = cg[4], z1 = cg[5];
        float w0 = fmaf(x0, x0, fmaf(y0, y0, z0 * z0));
        float w1 = fmaf(x1, x1, fmaf(y1, y1, z1 * z1));
        sxy[tid] = make_ulonglong2(pk2(x0, x1), pk2(y0, y1));
        szw[tid] = make_ulonglong2(pk2(z0, z1), pk2(w0, w1));
    }

    // Queries: -2*p duplicated into packed registers (duplication is free).
    const int m0 = mc * MCHUNK;
    unsigned long long qx[Q], qy[Q], qz[Q];
    float mnE[Q], mnO[Q];
#pragma unroll
    for (int t = 0; t < Q; t++) {
        const float* pg = partial + ((size_t)b * M_ + m0 + tid + t * THREADS) * 3;
        float vx = -2.0f * pg[0], vy = -2.0f * pg[1], vz = -2.0f * pg[2];
        qx[t] = pk2(vx, vx);
        qy[t] = pk2(vy, vy);
        qz[t] = pk2(vz, vz);
        mnE[t] = 3.4e38f;
        mnO[t] = 3.4e38f;
    }
    __syncthreads();

    // Hot loop: per group (2 points): 2 LDS.128 + Q*(3 FFMA2 + 2 FMNMX).
    // All lanes read the same smem address -> broadcast, conflict-free.
#pragma unroll 4
    for (int g = 0; g < NGROUP; g++) {
        ulonglong2 A = sxy[g];   // {xx', yy'}
        ulonglong2 Bv = szw[g];  // {zz', ww'}
#pragma unroll
        for (int t = 0; t < Q; t++) {
            unsigned long long acc;
            FMA_F32X2(acc, qz[t], Bv.x, Bv.y);
            FMA_F32X2(acc, qy[t], A.y, acc);
            FMA_F32X2(acc, qx[t], A.x, acc);
            float lo, hi;
            unpk2(lo, hi, acc);
            mnE[t] = fminf(mnE[t], lo);   // even-point chain
            mnO[t] = fminf(mnO[t], hi);   // odd-point chain (independent)
        }
    }

#pragma unroll
    for (int t = 0; t < Q; t++) {
        g_minbuf[ns][b * M_ + m0 + tid + t * THREADS] = fminf(mnE[t], mnO[t]);
    }
}

// k2: combine splits, sqrt, block-reduce; last-arriving CTA does the final
// 128-slot sum in fixed order (deterministic) and resets the counter.
__global__ void __launch_bounds__(K2_THREADS)
k2_reduce(const float* __restrict__ partial, float* __restrict__ out) {
    __shared__ float ssum[K2_THREADS];
    __shared__ int is_last;
    const int tid = threadIdx.x;
    const int pid = blockIdx.x * K2_THREADS + tid;  // pid = b*M + m

    float s = g_minbuf[0][pid];
#pragma unroll
    for (int k = 1; k < NSPLIT; k++) s = fminf(s, g_minbuf[k][pid]);

    const float* pg = partial + (size_t)pid * 3;
    float psq = fmaf(pg[0], pg[0], fmaf(pg[1], pg[1], pg[2] * pg[2]));
    float d   = sqrtf(fmaxf(psq + s, 0.0f));

    ssum[tid] = d;
    __syncthreads();
#pragma unroll
    for (int off = K2_THREADS / 2; off > 0; off >>= 1) {
        if (tid < off) ssum[tid] += ssum[tid + off];
        __syncthreads();
    }
    if (tid == 0) {
        g_blocksum[blockIdx.x] = ssum[0];
        __threadfence();
        unsigned int ticket = atomicAdd(&g_cnt, 1u);
        is_last = (ticket == K2_GRID - 1);
    }
    __syncthreads();

    if (is_last) {
        // All other CTAs' g_blocksum writes are visible (fence before the
        // ticket that made us last).
        if (tid < K2_GRID) ssum[tid] = g_blocksum[tid];
        __syncthreads();
#pragma unroll
        for (int off = K2_GRID / 2; off > 0; off >>= 1) {
            if (tid < off) ssum[tid] += ssum[tid + off];
            __syncthreads();
        }
        if (tid == 0) {
            out[0] = ssum[0] * (1.0f / (float)TOTAL_P);
            g_cnt = 0;  // restore state for next (graph-replayed) launch
        }
    }
}

extern "C" void kernel_launch(void* const* d_in, const int* in_sizes, int n_in,
                              void* d_out, int out_size) {
    const float* completed = (const float*)d_in[0];  // (8, 8192, 3)
    const float* partial   = (const float*)d_in[1];  // (8, 4096, 3)
    if (n_in >= 2 && in_sizes[0] == B_ * M_ * 3 && in_sizes[1] == B_ * N_ * 3) {
        completed = (const float*)d_in[1];
        partial   = (const float*)d_in[0];
    }

    k1_min_tile<<<K1_GRID, THREADS>>>(completed, partial);
    k2_reduce<<<K2_GRID, K2_THREADS>>>(partial, (float*)d_out);
}